// round 12
// baseline (speedup 1.0000x reference)
#include <cuda_runtime.h>
#include <cuda_bf16.h>
#include <cstdint>

// Problem constants (shapes fixed by the dataset; sizes re-derived from in_sizes)
#define MAX_NODES 100000
#define MAX_EDGES 1600000
#define IN_DIM    64
#define HID_DIM   32
#define SCAN_TILE 1024
#define MAX_PARTIALS 128          // supports n <= 131072
#define NUM_BARRIERS 8

// Scratch (allocation-free rule: __device__ globals)
__device__ int   g_deg_out[MAX_NODES];
__device__ int   g_deg_in [MAX_NODES];
__device__ int   g_row_ptr[MAX_NODES + 1];
__device__ int   g_cursor [MAX_NODES];
__device__ int   g_partial[MAX_PARTIALS];
__device__ int   g_csr_src[MAX_EDGES];
__device__ float g_h      [MAX_NODES * HID_DIM];   // (X@W) * norm_src
__device__ volatile unsigned int g_bar[NUM_BARRIERS];  // monotonic barrier tokens

// ---------------------------------------------------------------------------
// Grid barrier: monotonic token scheme, safe across CUDA-graph replays
// (counters only grow; each use consumes exactly gridDim.x tokens).
// Spin is a volatile read (no atomic) to avoid L2 atomic-ALU serialization
// across 444 polling blocks; arrive is a single atomicAdd.
// ---------------------------------------------------------------------------
__device__ __forceinline__ void grid_barrier(int slot) {
    __syncthreads();
    if (threadIdx.x == 0) {
        __threadfence();                                   // release prior writes
        unsigned nb = gridDim.x;
        unsigned token = atomicAdd((unsigned int*)&g_bar[slot], 1u);
        unsigned target = (token / nb + 1u) * nb;
        unsigned backoff = 32;
        while (g_bar[slot] < target) {
            __nanosleep(backoff);
            if (backoff < 1024) backoff <<= 1;
        }
        __threadfence();                                   // acquire others' writes
    }
    __syncthreads();
}

// ---------------------------------------------------------------------------
// One persistent kernel, 6 phases. Grid = 148*3 blocks x 256 threads,
// __launch_bounds__(256,3) guarantees co-residency for the grid barrier.
// ---------------------------------------------------------------------------
__global__ void __launch_bounds__(256, 3)
k_gcn_fused(const float* __restrict__ X,
            const int*   __restrict__ src,
            const int*   __restrict__ dst,
            const float* __restrict__ W,
            const float* __restrict__ b,
            float*       __restrict__ out,
            int n, int E) {
    __shared__ float sW[IN_DIM * HID_DIM];   // 8 KB (gemm phase)
    __shared__ int   sw[256];                // scan phase
    __shared__ int   s_off;

    const int tid     = threadIdx.x;
    const int gtid    = blockIdx.x * blockDim.x + tid;
    const int gstride = gridDim.x * blockDim.x;

    // ---------------- Phase 0: zero degree counters (int4) ----------------
    {
        int n4 = n >> 2;
        int4 z = make_int4(0, 0, 0, 0);
        for (int i = gtid; i < n4; i += gstride) {
            reinterpret_cast<int4*>(g_deg_out)[i] = z;
            reinterpret_cast<int4*>(g_deg_in )[i] = z;
        }
        if (gtid < (n & 3)) {
            int t = n4 * 4 + gtid;
            g_deg_out[t] = 0; g_deg_in[t] = 0;
        }
    }
    grid_barrier(0);

    // ---------------- Phase 1: fused degree histograms (4 edges/unit) -----
    {
        int units = (E + 3) / 4;
        for (int u = gtid; u < units; u += gstride) {
            int base = u * 4;
            if (base + 3 < E) {
                int4 s = __ldg(reinterpret_cast<const int4*>(src + base));
                int4 d = __ldg(reinterpret_cast<const int4*>(dst + base));
                atomicAdd(&g_deg_out[s.x], 1); atomicAdd(&g_deg_in[d.x], 1);
                atomicAdd(&g_deg_out[s.y], 1); atomicAdd(&g_deg_in[d.y], 1);
                atomicAdd(&g_deg_out[s.z], 1); atomicAdd(&g_deg_in[d.z], 1);
                atomicAdd(&g_deg_out[s.w], 1); atomicAdd(&g_deg_in[d.w], 1);
            } else {
                for (int i = base; i < E; i++) {
                    atomicAdd(&g_deg_out[__ldg(src + i)], 1);
                    atomicAdd(&g_deg_in [__ldg(dst + i)], 1);
                }
            }
        }
    }
    grid_barrier(1);

    // ---------------- Phase 2a: per-tile local scan ------------------------
    int nt = (n + SCAN_TILE - 1) / SCAN_TILE;   // tiles (98)
    for (int t = blockIdx.x; t < nt; t += gridDim.x) {
        int idx = t * SCAN_TILE + tid * 4;
        int v0 = 0, v1 = 0, v2 = 0, v3 = 0;
        if (idx + 3 < n) {
            int4 v = *reinterpret_cast<const int4*>(g_deg_in + idx);
            v0 = v.x; v1 = v.y; v2 = v.z; v3 = v.w;
        } else {
            if (idx + 0 < n) v0 = g_deg_in[idx + 0];
            if (idx + 1 < n) v1 = g_deg_in[idx + 1];
            if (idx + 2 < n) v2 = g_deg_in[idx + 2];
        }
        sw[tid] = v0 + v1 + v2 + v3;
        __syncthreads();
        for (int off = 1; off < 256; off <<= 1) {
            int u = (tid >= off) ? sw[tid - off] : 0;
            __syncthreads();
            sw[tid] += u;
            __syncthreads();
        }
        int excl = (tid == 0) ? 0 : sw[tid - 1];
        if (idx + 0 < n) g_row_ptr[idx + 0] = excl;
        if (idx + 1 < n) g_row_ptr[idx + 1] = excl + v0;
        if (idx + 2 < n) g_row_ptr[idx + 2] = excl + v0 + v1;
        if (idx + 3 < n) g_row_ptr[idx + 3] = excl + v0 + v1 + v2;
        if (tid == 255) g_partial[t] = sw[255];
        __syncthreads();
    }
    grid_barrier(2);

    // ---------------- Phase 2b: add tile offsets, write cursor -------------
    for (int t = blockIdx.x; t < nt; t += gridDim.x) {
        if (tid < 32) {
            int sum = 0;
            for (int j = tid; j < t; j += 32) sum += g_partial[j];
#pragma unroll
            for (int off = 16; off > 0; off >>= 1)
                sum += __shfl_down_sync(0xffffffffu, sum, off);
            if (tid == 0) s_off = sum;
        }
        __syncthreads();
        int off = s_off;
        int idx = t * SCAN_TILE + tid * 4;
        if (idx + 3 < n) {
            int4 v = *reinterpret_cast<const int4*>(g_row_ptr + idx);
            v.x += off; v.y += off; v.z += off; v.w += off;
            *reinterpret_cast<int4*>(g_row_ptr + idx) = v;
            *reinterpret_cast<int4*>(g_cursor  + idx) = v;
        } else {
            for (int i = idx; i < n; i++) {
                int v = g_row_ptr[i] + off;
                g_row_ptr[i] = v;
                g_cursor[i]  = v;
            }
        }
        __syncthreads();
    }
    if (blockIdx.x == 0 && tid == 0) g_row_ptr[n] = E;
    grid_barrier(3);

    // ---------------- Phase 3: CSR fill (8 edges/unit, MLP=8 atomics) ------
    {
        int units = (E + 7) / 8;
        for (int u = gtid; u < units; u += gstride) {
            int base = u * 8;
            if (base + 7 < E) {
                int4 s0 = __ldg(reinterpret_cast<const int4*>(src + base));
                int4 s1 = __ldg(reinterpret_cast<const int4*>(src + base + 4));
                int4 d0 = __ldg(reinterpret_cast<const int4*>(dst + base));
                int4 d1 = __ldg(reinterpret_cast<const int4*>(dst + base + 4));
                int p0 = atomicAdd(&g_cursor[d0.x], 1);
                int p1 = atomicAdd(&g_cursor[d0.y], 1);
                int p2 = atomicAdd(&g_cursor[d0.z], 1);
                int p3 = atomicAdd(&g_cursor[d0.w], 1);
                int p4 = atomicAdd(&g_cursor[d1.x], 1);
                int p5 = atomicAdd(&g_cursor[d1.y], 1);
                int p6 = atomicAdd(&g_cursor[d1.z], 1);
                int p7 = atomicAdd(&g_cursor[d1.w], 1);
                g_csr_src[p0] = s0.x; g_csr_src[p1] = s0.y;
                g_csr_src[p2] = s0.z; g_csr_src[p3] = s0.w;
                g_csr_src[p4] = s1.x; g_csr_src[p5] = s1.y;
                g_csr_src[p6] = s1.z; g_csr_src[p7] = s1.w;
            } else {
                for (int i = base; i < E; i++) {
                    int p = atomicAdd(&g_cursor[__ldg(dst + i)], 1);
                    g_csr_src[p] = __ldg(src + i);
                }
            }
        }
    }
    grid_barrier(4);

    // ---------------- Phase 4: h = (X@W) * rsqrt(max(deg_out,1)) -----------
    {
        for (int i = tid; i < IN_DIM * HID_DIM; i += blockDim.x)
            sW[i] = W[i];
        __syncthreads();

        for (int r = gtid; r < n; r += gstride) {
            float acc[HID_DIM];
#pragma unroll
            for (int j = 0; j < HID_DIM; j++) acc[j] = 0.f;

            const float4* xr = reinterpret_cast<const float4*>(X + (size_t)r * IN_DIM);
#pragma unroll 4
            for (int k4 = 0; k4 < IN_DIM / 4; k4++) {
                float4 x = __ldg(xr + k4);
                int k = k4 * 4;
#pragma unroll
                for (int j = 0; j < HID_DIM; j++) {
                    acc[j] = fmaf(x.x, sW[(k + 0) * HID_DIM + j],
                             fmaf(x.y, sW[(k + 1) * HID_DIM + j],
                             fmaf(x.z, sW[(k + 2) * HID_DIM + j],
                             fmaf(x.w, sW[(k + 3) * HID_DIM + j], acc[j]))));
                }
            }

            float nrm = rsqrtf(fmaxf((float)g_deg_out[r], 1.0f));
            float4* hr = reinterpret_cast<float4*>(g_h + (size_t)r * HID_DIM);
#pragma unroll
            for (int j4 = 0; j4 < HID_DIM / 4; j4++) {
                float4 v;
                v.x = acc[j4 * 4 + 0] * nrm;
                v.y = acc[j4 * 4 + 1] * nrm;
                v.z = acc[j4 * 4 + 2] * nrm;
                v.w = acc[j4 * 4 + 3] * nrm;
                hr[j4] = v;
            }
        }
    }
    grid_barrier(5);

    // ---------------- Phase 5: pull aggregation + finalize ------------------
    // One warp per node, grid-stride over nodes. g = lane>>3 (edge sub-slot),
    // p = lane&7 (float4 slice). Edge loop unrolled x2 for MLP.
    {
        int lane = tid & 31;
        int p = lane & 7;
        int g = lane >> 3;
        int warpId  = gtid >> 5;
        int nwarps  = gstride >> 5;
        const float4* h4 = reinterpret_cast<const float4*>(g_h);
        float4 bb = __ldg(reinterpret_cast<const float4*>(b) + p);

        for (int node = warpId; node < n; node += nwarps) {
            int start = __ldg(&g_row_ptr[node]);
            int end   = __ldg(&g_row_ptr[node + 1]);

            float4 acc = make_float4(0.f, 0.f, 0.f, 0.f);
            int j = start + g;
            for (; j + 4 < end; j += 8) {
                int s0 = __ldg(&g_csr_src[j]);
                int s1 = __ldg(&g_csr_src[j + 4]);
                float4 v0 = __ldg(h4 + (size_t)s0 * (HID_DIM / 4) + p);
                float4 v1 = __ldg(h4 + (size_t)s1 * (HID_DIM / 4) + p);
                acc.x += v0.x + v1.x;
                acc.y += v0.y + v1.y;
                acc.z += v0.z + v1.z;
                acc.w += v0.w + v1.w;
            }
            if (j < end) {
                int s = __ldg(&g_csr_src[j]);
                float4 v = __ldg(h4 + (size_t)s * (HID_DIM / 4) + p);
                acc.x += v.x; acc.y += v.y; acc.z += v.z; acc.w += v.w;
            }

#pragma unroll
            for (int off = 16; off >= 8; off >>= 1) {
                acc.x += __shfl_down_sync(0xffffffffu, acc.x, off);
                acc.y += __shfl_down_sync(0xffffffffu, acc.y, off);
                acc.z += __shfl_down_sync(0xffffffffu, acc.z, off);
                acc.w += __shfl_down_sync(0xffffffffu, acc.w, off);
            }

            if (g == 0) {
                float nrm = rsqrtf(fmaxf((float)(end - start), 1.0f));
                float4 v;
                v.x = fmaxf(acc.x * nrm + bb.x, 0.f);
                v.y = fmaxf(acc.y * nrm + bb.y, 0.f);
                v.z = fmaxf(acc.z * nrm + bb.z, 0.f);
                v.w = fmaxf(acc.w * nrm + bb.w, 0.f);
                reinterpret_cast<float4*>(out)[(size_t)node * (HID_DIM / 4) + p] = v;
            }
        }
    }
}

// ---------------------------------------------------------------------------
extern "C" void kernel_launch(void* const* d_in, const int* in_sizes, int n_in,
                              void* d_out, int out_size) {
    const float* features = (const float*)d_in[0];
    const int*   src      = (const int*)  d_in[1];
    const int*   dst      = (const int*)  d_in[2];
    const float* W        = (const float*)d_in[3];
    const float* b        = (const float*)d_in[4];
    float*       out      = (float*)d_out;

    int n = in_sizes[0] / IN_DIM;   // 100000
    int E = in_sizes[1];            // 1600000

    // 148 SMs x 3 co-resident CTAs (guaranteed by __launch_bounds__(256,3);
    // GB300 has 152 SMs so wave 1 always holds the whole grid).
    int nb = 148 * 3;
    k_gcn_fused<<<nb, 256>>>(features, src, dst, W, b, out, n, E);
}

// round 13
// speedup vs baseline: 1.4587x; 1.4587x over previous
#include <cuda_runtime.h>
#include <cuda_bf16.h>
#include <cstdint>

// Problem constants (shapes fixed by the dataset; sizes re-derived from in_sizes)
#define MAX_NODES 100000
#define IN_DIM    64
#define HID_DIM   32

// Scratch (allocation-free rule: __device__ globals).
// NOTE: device globals are zero-initialized at module load, and k_finalize
// re-zeros both degree arrays after consuming them, so every kernel_launch
// call (correctness run, graph capture, every replay) starts from zeroed
// counters without a dedicated zeroing pass.
__device__ int   g_deg_out[MAX_NODES];
__device__ int   g_deg_in [MAX_NODES];
__device__ float g_h      [MAX_NODES * HID_DIM];   // (X@W) * norm_src

// ---------------------------------------------------------------------------
// K1: zero the output accumulator (d_out is poisoned) + out-degree histogram.
//     The two touch disjoint arrays -> safe in one kernel, no ordering needed.
//     Histogram: 4 edges/unit via int4 loads (4 independent REDGs in flight).
// ---------------------------------------------------------------------------
__global__ void k_zero_hist(float4* __restrict__ out4,
                            const int* __restrict__ src,
                            int n, int E) {
    int tid = blockIdx.x * blockDim.x + threadIdx.x;
    int gstride = gridDim.x * blockDim.x;

    // zero out: n*8 float4 units
    int tot4 = n * (HID_DIM / 4);
    float4 z = make_float4(0.f, 0.f, 0.f, 0.f);
    for (int i = tid; i < tot4; i += gstride)
        out4[i] = z;

    // out-degree histogram: E/4 units
    int units = (E + 3) / 4;
    for (int u = tid; u < units; u += gstride) {
        int base = u * 4;
        if (base + 3 < E) {
            int4 s = __ldg(reinterpret_cast<const int4*>(src + base));
            atomicAdd(&g_deg_out[s.x], 1);
            atomicAdd(&g_deg_out[s.y], 1);
            atomicAdd(&g_deg_out[s.z], 1);
            atomicAdd(&g_deg_out[s.w], 1);
        } else {
            for (int i = base; i < E; i++)
                atomicAdd(&g_deg_out[__ldg(src + i)], 1);
        }
    }
}

// ---------------------------------------------------------------------------
// K2: h = (X @ W) * rsqrt(max(deg_out,1))
//     One row per thread; W staged in smem (all-thread broadcast reads).
// ---------------------------------------------------------------------------
__global__ void k_gemm_norm(const float* __restrict__ X,
                            const float* __restrict__ W,
                            int n) {
    __shared__ float sW[IN_DIM * HID_DIM];   // 8 KB
    for (int i = threadIdx.x; i < IN_DIM * HID_DIM; i += blockDim.x)
        sW[i] = W[i];
    __syncthreads();

    int r = blockIdx.x * blockDim.x + threadIdx.x;
    if (r >= n) return;

    float acc[HID_DIM];
#pragma unroll
    for (int j = 0; j < HID_DIM; j++) acc[j] = 0.f;

    const float4* xr = reinterpret_cast<const float4*>(X + (size_t)r * IN_DIM);
#pragma unroll 4
    for (int k4 = 0; k4 < IN_DIM / 4; k4++) {
        float4 x = __ldg(xr + k4);
        int k = k4 * 4;
#pragma unroll
        for (int j = 0; j < HID_DIM; j++) {
            acc[j] = fmaf(x.x, sW[(k + 0) * HID_DIM + j],
                     fmaf(x.y, sW[(k + 1) * HID_DIM + j],
                     fmaf(x.z, sW[(k + 2) * HID_DIM + j],
                     fmaf(x.w, sW[(k + 3) * HID_DIM + j], acc[j]))));
        }
    }

    float nrm = rsqrtf(fmaxf((float)g_deg_out[r], 1.0f));
    float4* hr = reinterpret_cast<float4*>(g_h + (size_t)r * HID_DIM);
#pragma unroll
    for (int j4 = 0; j4 < HID_DIM / 4; j4++) {
        float4 v;
        v.x = acc[j4 * 4 + 0] * nrm;
        v.y = acc[j4 * 4 + 1] * nrm;
        v.z = acc[j4 * 4 + 2] * nrm;
        v.w = acc[j4 * 4 + 3] * nrm;
        hr[j4] = v;
    }
}

// ---------------------------------------------------------------------------
// K3: scatter  out[dst] += h[src]  (+ in-degree count, lane p==0 per edge).
//     8 threads / edge, one float4 each: coalesced 128B gather,
//     vector red.global.add.v4.f32 (4x fewer LSU red ops vs scalar atomicAdd).
//     This kernel sits at the REDG throughput floor (~12.8M + 1.6M red ops).
// ---------------------------------------------------------------------------
__global__ void k_scatter(const int* __restrict__ src,
                          const int* __restrict__ dst,
                          float* __restrict__ out,
                          int E) {
    long long tid = (long long)blockIdx.x * blockDim.x + threadIdx.x;
    int e = (int)(tid >> 3);
    if (e >= E) return;
    int p = (int)(tid & 7);

    int s = __ldg(src + e);
    int d = __ldg(dst + e);

    float4 v = __ldg(reinterpret_cast<const float4*>(g_h + (size_t)s * HID_DIM) + p);
    float* addr = out + (size_t)d * HID_DIM + p * 4;

    asm volatile("red.global.add.v4.f32 [%0], {%1, %2, %3, %4};"
                 :: "l"(addr), "f"(v.x), "f"(v.y), "f"(v.z), "f"(v.w)
                 : "memory");

    if (p == 0)
        atomicAdd(&g_deg_in[d], 1);      // consumed by k_finalize (after sync)
}

// ---------------------------------------------------------------------------
// K4: out = relu(out * rsqrt(max(deg_in,1)) + b)   (in place, vectorized)
//     Also re-zeros both degree arrays for the next kernel_launch call.
// ---------------------------------------------------------------------------
__global__ void k_finalize(float4* __restrict__ out4,
                           const float* __restrict__ b,
                           int n) {
    __shared__ float4 sb[HID_DIM / 4];
    if (threadIdx.x < HID_DIM / 4)
        sb[threadIdx.x] = reinterpret_cast<const float4*>(b)[threadIdx.x];
    __syncthreads();

    int tot4 = n * (HID_DIM / 4);
    int i = blockIdx.x * blockDim.x + threadIdx.x;
    if (i >= tot4) return;

    int row = i >> 3;
    int j4  = i & 7;
    float nrm = rsqrtf(fmaxf((float)g_deg_in[row], 1.0f));
    float4 v  = out4[i];
    float4 bb = sb[j4];
    v.x = fmaxf(v.x * nrm + bb.x, 0.f);
    v.y = fmaxf(v.y * nrm + bb.y, 0.f);
    v.z = fmaxf(v.z * nrm + bb.z, 0.f);
    v.w = fmaxf(v.w * nrm + bb.w, 0.f);
    out4[i] = v;

    // Reset counters for the next launch (one thread per row: j4 == 0)
    if (j4 == 0) {
        g_deg_in[row]  = 0;
        g_deg_out[row] = 0;
    }
}

// ---------------------------------------------------------------------------
extern "C" void kernel_launch(void* const* d_in, const int* in_sizes, int n_in,
                              void* d_out, int out_size) {
    const float* features = (const float*)d_in[0];
    const int*   src      = (const int*)  d_in[1];
    const int*   dst      = (const int*)  d_in[2];
    const float* W        = (const float*)d_in[3];
    const float* b        = (const float*)d_in[4];
    float*       out      = (float*)d_out;

    int n = in_sizes[0] / IN_DIM;   // 100000
    int E = in_sizes[1];            // 1600000

    const int B = 256;

    // K1: zero out + out-degree histogram (grid-stride over both)
    k_zero_hist<<<1184, B>>>((float4*)out, src, n, E);   // 148 SMs x 8 CTAs

    // K2: gemm + src-norm
    k_gemm_norm<<<(n + B - 1) / B, B>>>(features, W, n);

    // K3: scatter (8 threads per edge) + in-degree count
    long long threads3 = (long long)E * 8;
    k_scatter<<<(int)((threads3 + B - 1) / B), B>>>(src, dst, out, E);

    // K4: finalize + counter reset
    int tot4 = n * (HID_DIM / 4);
    k_finalize<<<(tot4 + B - 1) / B, B>>>((float4*)out, b, n);
}